// round 15
// baseline (speedup 1.0000x reference)
#include <cuda_runtime.h>
#include <math.h>

// Problem constants
#define Bc   512
#define NAc  128
#define NLc  512
#define Dc   128
#define KAc  16
#define KLc  16
#define NNODES 32   // KA + KL

typedef unsigned long long u64;
typedef unsigned int u32;
#define KMAX 0xFFFFFFFFFFFFFFFFull

// ---------------------------------------------------------------------------
// Dynamic shared layout (53456 bytes -> 4 blocks/SM)
//   Xs/Hs: float [128][36], transposed [k][row] (stride 36 floats)
//   Wst:   float [2][2048] double-buffered weight stage
//   ssel:  int[32];  bm: u32[20] (4 actor-bitmap words + 16 lane-bitmap words)
//   Select-phase overlays on Hs: keysA[128] u64, cand[64] u64, ax/ay[16]
// ---------------------------------------------------------------------------
#define SM_XS    0        // 18432
#define SM_HS    18432    // 18432
#define SM_WST   36864    // 16384
#define SM_SSEL  53248    // 128
#define SM_BM    53376    // 80
#define SM_TOTAL 53456

// ---------------------------------------------------------------------------
// helpers
// ---------------------------------------------------------------------------
__device__ __forceinline__ u64 pk2(float lo, float hi) {
    u64 r;
    asm("mov.b64 %0, {%1, %2};" : "=l"(r) : "f"(lo), "f"(hi));
    return r;
}
__device__ __forceinline__ void fma2(u64& d, u64 a, u64 b) {
    asm("fma.rn.f32x2 %0, %1, %2, %0;" : "+l"(d) : "l"(a), "l"(b));
}
__device__ __forceinline__ void unpk2(u64 v, float& lo, float& hi) {
    asm("mov.b64 {%0, %1}, %2;" : "=f"(lo), "=f"(hi) : "l"(v));
}
__device__ __forceinline__ void cpa16(void* smem_dst, const void* gsrc) {
    unsigned sa = (unsigned)__cvta_generic_to_shared(smem_dst);
    asm volatile("cp.async.cg.shared.global [%0], [%1], 16;"
                 :: "r"(sa), "l"(gsrc));
}
#define CP_COMMIT() asm volatile("cp.async.commit_group;")
#define CP_WAIT0()  asm volatile("cp.async.wait_group 0;")

__device__ __forceinline__ float wsum32(float v) {
    #pragma unroll
    for (int o = 16; o > 0; o >>= 1) v += __shfl_xor_sync(0xffffffffu, v, o);
    return v;
}
__device__ __forceinline__ float gelu_exact(float x) {
    return 0.5f * x * (1.0f + erff(x * 0.70710678118654752440f));
}
// monotone float->uint map: f1 < f2  <=>  fmono(f1) < fmono(f2)  (incl. +-inf)
__device__ __forceinline__ u32 fmono(float f) {
    u32 u = __float_as_uint(f);
    return (u & 0x80000000u) ? ~u : (u | 0x80000000u);
}
__device__ __forceinline__ u64 umin64(u64 a, u64 b) { return a < b ? a : b; }

// Warp-collective: extract the 16 smallest of 128 unique keys (4/lane),
// ascending; emit(r, key) on lane 0.
template <typename EMIT>
__device__ __forceinline__ void warp_top16(u64 (&k)[4], EMIT emit, int lane) {
    #pragma unroll 1
    for (int r = 0; r < 16; r++) {
        u64 lm = umin64(umin64(k[0], k[1]), umin64(k[2], k[3]));
        #pragma unroll
        for (int o = 16; o > 0; o >>= 1)
            lm = umin64(lm, __shfl_xor_sync(0xffffffffu, lm, o));
        if      (k[0] == lm) k[0] = KMAX;
        else if (k[1] == lm) k[1] = KMAX;
        else if (k[2] == lm) k[2] = KMAX;
        else if (k[3] == lm) k[3] = KMAX;
        if (lane == 0) emit(r, lm);
    }
}

// ---------------------------------------------------------------------------
// 32x128 @ 128x128 GEMM, 128 threads, cp.async double-buffered W staging,
// software-pipelined inner loads (R13-proven).
// ---------------------------------------------------------------------------
__device__ __forceinline__ void gemm_rc8(
    const float* A, const float* __restrict__ Wg,
    float* Wst, int tid, int rg, int cg, u64 (&acc)[4][4])
{
    #pragma unroll
    for (int rp = 0; rp < 4; rp++)
        #pragma unroll
        for (int c = 0; c < 4; c++) acc[rp][c] = 0ull;

    #pragma unroll
    for (int i = 0; i < 4; i++)
        cpa16(Wst + (tid + 128 * i) * 4, Wg + (tid + 128 * i) * 4);
    CP_COMMIT();

    #pragma unroll 1
    for (int s = 0; s < 8; s++) {
        CP_WAIT0();
        __syncthreads();
        if (s < 7) {
            float* dst = Wst + ((s + 1) & 1) * 2048;
            const float* src = Wg + (s + 1) * 2048;
            #pragma unroll
            for (int i = 0; i < 4; i++)
                cpa16(dst + (tid + 128 * i) * 4, src + (tid + 128 * i) * 4);
            CP_COMMIT();
        }
        const float* Ws = Wst + (s & 1) * 2048;
        const float* Ab = A + s * 16 * 36 + 8 * rg;

        float4 w        = *(const float4*)(Ws + 4 * cg);
        ulonglong2 a01  = *(const ulonglong2*)(Ab);
        ulonglong2 a23  = *(const ulonglong2*)(Ab + 4);

        #pragma unroll
        for (int kk = 0; kk < 16; kk++) {
            float4 wn; ulonglong2 a01n, a23n;
            if (kk < 15) {
                wn   = *(const float4*)(Ws + (kk + 1) * 128 + 4 * cg);
                a01n = *(const ulonglong2*)(Ab + (kk + 1) * 36);
                a23n = *(const ulonglong2*)(Ab + (kk + 1) * 36 + 4);
            }
            u64 bx = pk2(w.x, w.x);
            u64 by = pk2(w.y, w.y);
            u64 bz = pk2(w.z, w.z);
            u64 bw = pk2(w.w, w.w);
            fma2(acc[0][0], a01.x, bx); fma2(acc[0][1], a01.x, by);
            fma2(acc[0][2], a01.x, bz); fma2(acc[0][3], a01.x, bw);
            fma2(acc[1][0], a01.y, bx); fma2(acc[1][1], a01.y, by);
            fma2(acc[1][2], a01.y, bz); fma2(acc[1][3], a01.y, bw);
            fma2(acc[2][0], a23.x, bx); fma2(acc[2][1], a23.x, by);
            fma2(acc[2][2], a23.x, bz); fma2(acc[2][3], a23.x, bw);
            fma2(acc[3][0], a23.y, bx); fma2(acc[3][1], a23.y, by);
            fma2(acc[3][2], a23.y, bz); fma2(acc[3][3], a23.y, bw);
            if (kk < 15) { w = wn; a01 = a01n; a23 = a23n; }
        }
    }
}

// ---------------------------------------------------------------------------
// ONE kernel: select -> [copy lane rows] -> MLP -> scatter -> [copy actor rows]
// Block b owns batch b's entire output region; copy skips selected rows
// (bitmap) which the epilogue writes with computed values. Disjoint addresses.
// ---------------------------------------------------------------------------
__global__ void __launch_bounds__(128, 4)
fused_kernel(const float* __restrict__ actor_feat,
             const float* __restrict__ lane_feat,
             const float* __restrict__ lane_centers,
             const float* __restrict__ x_centers,
             const float* __restrict__ spike_rate,
             const void*  __restrict__ actor_valid_raw,
             const void*  __restrict__ lane_valid_raw,
             const float* __restrict__ W0a, const float* __restrict__ b0a,
             const float* __restrict__ W0b, const float* __restrict__ b0b,
             const float* __restrict__ W1a, const float* __restrict__ b1a,
             const float* __restrict__ W1b, const float* __restrict__ b1b,
             const float* __restrict__ gmm, const float* __restrict__ bta,
             float* __restrict__ out)
{
    extern __shared__ unsigned char smem_raw[];
    float* Xs  = (float*)(smem_raw + SM_XS);    // [k][row], stride 36
    float* Hs  = (float*)(smem_raw + SM_HS);
    float* Wst = (float*)(smem_raw + SM_WST);
    int*  ssel = (int*)(smem_raw + SM_SSEL);
    u32*  bmA  = (u32*)(smem_raw + SM_BM);        // [4]  actor-row bitmap
    u32*  bmL  = (u32*)(smem_raw + SM_BM) + 4;    // [16] lane-row bitmap
    // select-phase overlays on Hs (dead once GEMMs start)
    u64*   keysA = (u64*)Hs;                    // [128]
    u64*   cand  = (u64*)((char*)Hs + 1024);    // [64]
    float* ax    = (float*)((char*)Hs + 1536);  // [16]
    float* ay    = (float*)((char*)Hs + 1600);  // [16]

    const int tid  = threadIdx.x;
    const int b    = blockIdx.x;
    const int wid  = tid >> 5;
    const int lane = tid & 31;
    const int rg   = wid;        // GEMM: rows 8rg..8rg+7
    const int cg   = lane;       // GEMM: cols 4cg..4cg+3

    const size_t lane_base = (size_t)Bc * NAc * Dc;

    if (tid < 20) ((u32*)(smem_raw + SM_BM))[tid] = 0;   // zero bitmaps

    // ============ Phase 0: detect boolean encoding (u8 / i32 / f32) ========
    int enc;
    {
        const unsigned char* p =
            (const unsigned char*)lane_valid_raw + (size_t)b * 512;
        unsigned char b1 = p[tid * 4 + 1];
        unsigned char b2 = p[tid * 4 + 2];
        unsigned char b3 = p[tid * 4 + 3];
        int any1   = __syncthreads_or((int)b1);
        int anyOff = __syncthreads_or((int)(b1 | b2 | b3));
        enc = anyOff ? (any1 ? 0 : 2) : 1;
    }

    // ============ Phase A: actor top-16 (tournament, jax tie rule) =========
    {
        bool av;
        if (enc == 0)      av = ((const unsigned char*)actor_valid_raw)[(size_t)b * NAc + tid] != 0;
        else if (enc == 1) av = ((const int*)actor_valid_raw)[(size_t)b * NAc + tid] != 0;
        else               av = ((const float*)actor_valid_raw)[(size_t)b * NAc + tid] != 0.0f;
        float v = av ? spike_rate[b * NAc + tid] : -INFINITY;
        keysA[tid] = ((u64)(~fmono(v)) << 32) | (u32)tid;   // desc val, low idx
    }
    __syncthreads();
    if (wid == 0) {
        u64 k[4] = { keysA[lane], keysA[lane + 32],
                     keysA[lane + 64], keysA[lane + 96] };
        warp_top16(k, [&](int r, u64 gm) {
            ssel[r] = (int)(gm & 0xFFFFFFFFull);
        }, lane);
    }
    __syncthreads();
    if (tid < KAc) {
        int a = ssel[tid];
        ax[tid] = x_centers[((size_t)b * NAc + a) * 2 + 0];
        ay[tid] = x_centers[((size_t)b * NAc + a) * 2 + 1];
    }
    __syncthreads();

    // ============ Phase B: lane distances + top-16 (tournament) ============
    {
        u64 k[4];
        #pragma unroll
        for (int q = 0; q < 4; q++) {
            int l = 128 * wid + lane + 32 * q;
            bool lv;
            if (enc == 0)      lv = ((const unsigned char*)lane_valid_raw)[(size_t)b * NLc + l] != 0;
            else if (enc == 1) lv = ((const int*)lane_valid_raw)[(size_t)b * NLc + l] != 0;
            else               lv = ((const float*)lane_valid_raw)[(size_t)b * NLc + l] != 0.0f;
            float d = INFINITY;
            if (lv) {
                float lx = lane_centers[((size_t)b * NLc + l) * 2 + 0];
                float ly = lane_centers[((size_t)b * NLc + l) * 2 + 1];
                float m2 = INFINITY;
                #pragma unroll
                for (int a = 0; a < KAc; a++) {
                    float dx = __fadd_rn(ax[a], -lx);
                    float dy = __fadd_rn(ay[a], -ly);
                    float s = __fadd_rn(__fmul_rn(dx, dx), __fmul_rn(dy, dy));
                    m2 = fminf(m2, s);
                }
                d = sqrtf(m2);   // sqrt monotone: min(sqrt) == sqrt(min)
            }
            k[q] = ((u64)fmono(d) << 32) | (u32)l;
        }
        warp_top16(k, [&](int r, u64 gm) {
            cand[wid * 16 + r] = gm;
        }, lane);
    }
    __syncthreads();
    if (tid < 64) {   // merge 4x16 unique keys by rank count
        u64 mk = cand[tid];
        int cnt = 0;
        #pragma unroll 8
        for (int j = 0; j < 64; j++) cnt += (cand[j] < mk);
        if (cnt < KLc) ssel[KAc + cnt] = (int)(mk & 0xFFFFFFFFull);
    }
    __syncthreads();

    // bitmap of selected rows (skipped by the copy phases)
    if (tid < KAc) {
        int r = ssel[tid];
        atomicOr(&bmA[r >> 5], 1u << (r & 31));
    } else if (tid < NNODES) {
        int l = ssel[tid];
        atomicOr(&bmL[l >> 5], 1u << (l & 31));
    }

    // ============ Phase C: gather nodes (transposed into Xs) ===============
    #pragma unroll 4
    for (int rw = 0; rw < NNODES; rw++) {
        int idx = ssel[rw];
        const float* src = (rw < KAc)
            ? (actor_feat + ((size_t)b * NAc + idx) * Dc)
            : (lane_feat  + ((size_t)b * NLc + idx) * Dc);
        Xs[tid * 36 + rw] = src[tid];
    }
    __syncthreads();   // bitmaps + Xs visible

    // ============ Copy batch's LANE pool rows (skip selected) ==============
    {
        const float4* src = (const float4*)(lane_feat + (size_t)b * NLc * Dc);
        float4* dst = (float4*)(out + lane_base + (size_t)b * NLc * Dc);
        #pragma unroll 1
        for (int r0 = wid * 4; r0 < NLc; r0 += 16) {
            float4 v[4];
            #pragma unroll
            for (int j = 0; j < 4; j++)
                v[j] = src[(r0 + j) * 32 + lane];
            #pragma unroll
            for (int j = 0; j < 4; j++) {
                int r = r0 + j;
                if (!((bmL[r >> 5] >> (r & 31)) & 1u))
                    dst[r * 32 + lane] = v[j];
            }
        }
    }

    // ============ Phase D: 2 layers of residual MLP + LayerNorm ============
    u64 acc[4][4];

    #pragma unroll 1
    for (int layer = 0; layer < 2; layer++) {
        const float* Wa  = layer ? W1a : W0a;
        const float* ba  = layer ? b1a : b0a;
        const float* Wb2 = layer ? W1b : W0b;
        const float* bb2 = layer ? b1b : b0b;

        // ---- GEMM1: H = gelu(X @ Wa + ba) -> Hs ----
        gemm_rc8(Xs, Wa, Wst, tid, rg, cg, acc);
        {
            float4 bq = *(const float4*)(ba + 4 * cg);
            float bar[4] = {bq.x, bq.y, bq.z, bq.w};
            #pragma unroll
            for (int rp = 0; rp < 4; rp++) {
                int r0 = 8 * rg + 2 * rp;
                #pragma unroll
                for (int c = 0; c < 4; c++) {
                    float lo, hi; unpk2(acc[rp][c], lo, hi);
                    lo = gelu_exact(lo + bar[c]);
                    hi = gelu_exact(hi + bar[c]);
                    *(float2*)(Hs + (4 * cg + c) * 36 + r0) = make_float2(lo, hi);
                }
            }
        }
        // Hs writes vs GEMM2 reads: behind gemm_rc8's stage-0 sync

        // ---- GEMM2: Y = H @ Wb + bb; Z = LN(X + Y) ----
        gemm_rc8(Hs, Wb2, Wst, tid, rg, cg, acc);
        {
            float4 bq = *(const float4*)(bb2 + 4 * cg);
            float bbr[4] = {bq.x, bq.y, bq.z, bq.w};
            float4 gq = *(const float4*)(gmm + 4 * cg);
            float4 pq = *(const float4*)(bta + 4 * cg);
            float gar[4] = {gq.x, gq.y, gq.z, gq.w};
            float per[4] = {pq.x, pq.y, pq.z, pq.w};

            #pragma unroll
            for (int rp = 0; rp < 4; rp++) {
                int r0 = 8 * rg + 2 * rp;
                float l0[4], l1[4];
                #pragma unroll
                for (int c = 0; c < 4; c++) {
                    float lo, hi; unpk2(acc[rp][c], lo, hi);
                    float2 xv = *(const float2*)(Xs + (4 * cg + c) * 36 + r0);
                    l0[c] = lo + bbr[c] + xv.x;
                    l1[c] = hi + bbr[c] + xv.y;
                }
                float m0 = wsum32(l0[0] + l0[1] + l0[2] + l0[3]) * 0.0078125f;
                float m1 = wsum32(l1[0] + l1[1] + l1[2] + l1[3]) * 0.0078125f;
                float q0 = 0.f, q1 = 0.f;
                #pragma unroll
                for (int c = 0; c < 4; c++) {
                    float d0 = l0[c] - m0; q0 += d0 * d0;
                    float d1 = l1[c] - m1; q1 += d1 * d1;
                }
                float i0 = rsqrtf(wsum32(q0) * 0.0078125f + 1e-5f);
                float i1 = rsqrtf(wsum32(q1) * 0.0078125f + 1e-5f);

                if (layer == 0) {
                    #pragma unroll
                    for (int c = 0; c < 4; c++) {
                        float z0 = (l0[c] - m0) * i0 * gar[c] + per[c];
                        float z1 = (l1[c] - m1) * i1 * gar[c] + per[c];
                        *(float2*)(Xs + (4 * cg + c) * 36 + r0) = make_float2(z0, z1);
                    }
                } else {
                    // ---- direct scatter into out (copy skips these rows) --
                    float4 o0, o1;
                    o0.x = (l0[0] - m0) * i0 * gar[0] + per[0];
                    o0.y = (l0[1] - m0) * i0 * gar[1] + per[1];
                    o0.z = (l0[2] - m0) * i0 * gar[2] + per[2];
                    o0.w = (l0[3] - m0) * i0 * gar[3] + per[3];
                    o1.x = (l1[0] - m1) * i1 * gar[0] + per[0];
                    o1.y = (l1[1] - m1) * i1 * gar[1] + per[1];
                    o1.z = (l1[2] - m1) * i1 * gar[2] + per[2];
                    o1.w = (l1[3] - m1) * i1 * gar[3] + per[3];
                    int idx0 = ssel[r0];
                    int idx1 = ssel[r0 + 1];
                    float* d0 = (r0 < KAc)
                        ? out + ((size_t)b * NAc + idx0) * Dc
                        : out + lane_base + ((size_t)b * NLc + idx0) * Dc;
                    float* d1 = (r0 + 1 < KAc)
                        ? out + ((size_t)b * NAc + idx1) * Dc
                        : out + lane_base + ((size_t)b * NLc + idx1) * Dc;
                    *(float4*)(d0 + 4 * cg) = o0;
                    *(float4*)(d1 + 4 * cg) = o1;
                }
            }
        }
    }

    // ============ Copy batch's ACTOR pool rows (skip selected) =============
    {
        const float4* src = (const float4*)(actor_feat + (size_t)b * NAc * Dc);
        float4* dst = (float4*)(out + (size_t)b * NAc * Dc);
        #pragma unroll 1
        for (int r0 = wid * 4; r0 < NAc; r0 += 16) {
            float4 v[4];
            #pragma unroll
            for (int j = 0; j < 4; j++)
                v[j] = src[(r0 + j) * 32 + lane];
            #pragma unroll
            for (int j = 0; j < 4; j++) {
                int r = r0 + j;
                if (!((bmA[r >> 5] >> (r & 31)) & 1u))
                    dst[r * 32 + lane] = v[j];
            }
        }
    }
}

// ---------------------------------------------------------------------------
// kernel_launch: ONE kernel does everything.
// ---------------------------------------------------------------------------
extern "C" void kernel_launch(void* const* d_in, const int* in_sizes, int n_in,
                              void* d_out, int out_size)
{
    const float* actor_feat   = (const float*)d_in[0];
    const float* lane_feat    = (const float*)d_in[1];
    const float* lane_centers = (const float*)d_in[2];
    const float* x_centers    = (const float*)d_in[3];
    const float* spike_rate   = (const float*)d_in[4];
    const void*  actor_valid  = d_in[5];
    const void*  lane_valid   = d_in[6];
    const float* W0a = (const float*)d_in[7];
    const float* b0a = (const float*)d_in[8];
    const float* W0b = (const float*)d_in[9];
    const float* b0b = (const float*)d_in[10];
    const float* W1a = (const float*)d_in[11];
    const float* b1a = (const float*)d_in[12];
    const float* W1b = (const float*)d_in[13];
    const float* b1b = (const float*)d_in[14];
    const float* gmm = (const float*)d_in[15];
    const float* bta = (const float*)d_in[16];
    float* out = (float*)d_out;

    cudaFuncSetAttribute(fused_kernel,
                         cudaFuncAttributeMaxDynamicSharedMemorySize, SM_TOTAL);

    fused_kernel<<<Bc, 128, SM_TOTAL>>>(actor_feat, lane_feat, lane_centers,
                                        x_centers, spike_rate, actor_valid,
                                        lane_valid,
                                        W0a, b0a, W0b, b0b,
                                        W1a, b1a, W1b, b1b,
                                        gmm, bta, out);
}